// round 6
// baseline (speedup 1.0000x reference)
#include <cuda_runtime.h>
#include <cstdint>

#define DD 128
#define MAXROWS (2*50000)
#define MAXN 50001
#define MAXE 800000

// scratch (__device__ globals — allocation-free rule)
__device__ float g_m[MAXROWS * DD];
__device__ int   g_cnt[MAXN];
__device__ int   g_base[MAXN];
__device__ int   g_sorted[MAXE];
__device__ float g_Wm_pk[4 * 8192];   // W_msg  pre-split+packed: [ch][hi 4096 | lo 4096]
__device__ float g_Wu_pk[8 * 8192];   // W_upd  pre-split+packed

// ---------------------------------------------------------------------------
// helpers
// ---------------------------------------------------------------------------
__device__ __forceinline__ float to_tf32(float x) {
    uint32_t u;
    asm("cvt.rna.tf32.f32 %0, %1;" : "=r"(u) : "f"(x));
    return __uint_as_float(u);
}
__device__ __forceinline__ void split_tf32(float x, float& hi, float& lo) {
    hi = to_tf32(x);
    lo = to_tf32(x - hi);
}
__device__ __forceinline__ void mma_tf32(float* c, const float* a, const float* b) {
    asm volatile(
        "mma.sync.aligned.m16n8k8.row.col.f32.tf32.tf32.f32 "
        "{%0,%1,%2,%3}, {%4,%5,%6,%7}, {%8,%9}, {%0,%1,%2,%3};"
        : "+f"(c[0]), "+f"(c[1]), "+f"(c[2]), "+f"(c[3])
        : "r"(__float_as_uint(a[0])), "r"(__float_as_uint(a[1])),
          "r"(__float_as_uint(a[2])), "r"(__float_as_uint(a[3])),
          "r"(__float_as_uint(b[0])), "r"(__float_as_uint(b[1])));
}

// packed smem layout (floats)
//  A: [warp_m(2)][ks(4)][mt(2)][lane(32)][idx(4)]  = 2048 per buffer
//  B: [warp_n(4)][ks(4)][nt(4)][lane(32)][idx(2)]  = 4096 per buffer
#define PA_HI 0
#define PA_LO 2048
#define PB_HI 4096            // hi(4096) + lo(4096) contiguous
#define PACK_FLOATS 12288
#define AGG_OFF 12288         // update only: 64 x 132 agg tile
#define AGG_STR 132
#define MSG_SM_BYTES (PACK_FLOATS * 4)                      // 49152
#define UPD_SM_BYTES ((PACK_FLOATS + 64 * AGG_STR) * 4)     // 82944

// ============================================================================
// Kernel P: pre-split W into tf32 hi/lo, packed in B-fragment order.
// inner = (((warp_n*4+ks)*4+nt)*32+lane)*2 + khalf
// ============================================================================
__global__ __launch_bounds__(256) void presplit_k(
    const float* __restrict__ Wm, const float* __restrict__ Wu,
    float* __restrict__ pm, float* __restrict__ pu)
{
    const int i = blockIdx.x * 256 + threadIdx.x;
    if (i < 16384) {                   // W_msg [128][128]
        const int n = i >> 7, k = i & 127;
        const int ch = k >> 5, kk = k & 31;
        const int warp_n = n >> 5, nt = (n >> 3) & 3, g = n & 7;
        const int q = kk & 3, khalf = (kk >> 2) & 1, ks = kk >> 3;
        const int inner = (((warp_n * 4 + ks) * 4 + nt) * 32 + g * 4 + q) * 2 + khalf;
        float hi, lo;
        split_tf32(Wm[i], hi, lo);
        pm[ch * 8192 + inner] = hi;
        pm[ch * 8192 + 4096 + inner] = lo;
    }
    const int j = i - 16384;
    if (j >= 0 && j < 32768) {         // W_upd [128][256]
        const int n = j >> 8, k = j & 255;
        const int ch = k >> 5, kk = k & 31;
        const int warp_n = n >> 5, nt = (n >> 3) & 3, g = n & 7;
        const int q = kk & 3, khalf = (kk >> 2) & 1, ks = kk >> 3;
        const int inner = (((warp_n * 4 + ks) * 4 + nt) * 32 + g * 4 + q) * 2 + khalf;
        float hi, lo;
        split_tf32(Wu[j], hi, lo);
        pu[ch * 8192 + inner] = hi;
        pu[ch * 8192 + 4096 + inner] = lo;
    }
}

// ============================================================================
// Edge sort (counting sort by target)
// ============================================================================
__global__ __launch_bounds__(256) void hist_k(const int* __restrict__ etgt,
                                              int* __restrict__ cnt, int E)
{
    int e = blockIdx.x * blockDim.x + threadIdx.x;
    if (e < E) atomicAdd(&cnt[etgt[e]], 1);
}

__global__ __launch_bounds__(1024) void exscan_k(const int* __restrict__ cnt,
                                                 int* __restrict__ base, int n)
{
    __shared__ int ws[32];
    __shared__ int carry_s;
    const int tid = threadIdx.x;
    const int lane = tid & 31, wid = tid >> 5;
    if (tid == 0) carry_s = 0;
    __syncthreads();

    for (int chunk = 0; chunk < n; chunk += 1024) {
        const int i = chunk + tid;
        const int x = (i < n) ? cnt[i] : 0;
        int v = x;
        #pragma unroll
        for (int o = 1; o < 32; o <<= 1) {
            int t = __shfl_up_sync(0xffffffffu, v, o);
            if (lane >= o) v += t;
        }
        if (lane == 31) ws[wid] = v;
        __syncthreads();
        if (wid == 0) {
            int w = ws[lane];
            #pragma unroll
            for (int o = 1; o < 32; o <<= 1) {
                int t = __shfl_up_sync(0xffffffffu, w, o);
                if (lane >= o) w += t;
            }
            ws[lane] = w;
        }
        __syncthreads();
        const int woff = (wid > 0) ? ws[wid - 1] : 0;
        const int carry = carry_s;
        const int incl = v + woff + carry;
        if (i < n) base[i] = incl - x;
        __syncthreads();
        if (tid == 1023) carry_s = incl;
        __syncthreads();
    }
}

__global__ __launch_bounds__(256) void fill_k(
    const int* __restrict__ esrc, const int* __restrict__ etgt,
    const int* __restrict__ erel, int* __restrict__ base,
    int* __restrict__ sorted, int E)
{
    int e = blockIdx.x * blockDim.x + threadIdx.x;
    if (e >= E) return;
    const int t = etgt[e];
    const int pos = atomicAdd(&base[t], 1);
    sorted[pos] = esrc[e] | (erel[e] << 17);
}

// ---------------------------------------------------------------------------
// shared GEMM building blocks (fragment-packed smem)
// ---------------------------------------------------------------------------
// A staging: split one float4 of source row r, quad j (k = ch*32 + j*4 + q)
__device__ __forceinline__ void stage_A_f4(float* sm, int r, int j, float4 v)
{
    float4 hi, lo;
    split_tf32(v.x, hi.x, lo.x);
    split_tf32(v.y, hi.y, lo.y);
    split_tf32(v.z, hi.z, lo.z);
    split_tf32(v.w, hi.w, lo.w);
    const int warp_m = r >> 5, mt = (r >> 4) & 1, g = r & 7, hi8 = (r >> 3) & 1;
    const int khalf = j & 1, ks = j >> 1;
    const int basei = ((warp_m * 4 + ks) * 2 + mt) * 128 + g * 16 + (hi8 + 2 * khalf);
    float* ph = sm + PA_HI + basei;
    float* pl = sm + PA_LO + basei;
    ph[0] = hi.x; ph[4] = hi.y; ph[8] = hi.z; ph[12] = hi.w;
    pl[0] = lo.x; pl[4] = lo.y; pl[8] = lo.z; pl[12] = lo.w;
}

// warp-tile mma over one K=32 chunk from packed smem
__device__ __forceinline__ void mma_chunk(const float* sm, int warp_m, int warp_n,
                                          int lane, float c[2][4][4])
{
    #pragma unroll
    for (int ks = 0; ks < 4; ++ks) {
        float4 ah[2], al[2];
        #pragma unroll
        for (int mt = 0; mt < 2; ++mt) {
            const int off = ((warp_m * 4 + ks) * 2 + mt) * 128 + lane * 4;
            ah[mt] = *(const float4*)&sm[PA_HI + off];
            al[mt] = *(const float4*)&sm[PA_LO + off];
        }
        float2 bh[4], bl[4];
        #pragma unroll
        for (int nt = 0; nt < 4; ++nt) {
            const int off = ((warp_n * 4 + ks) * 4 + nt) * 64 + lane * 2;
            bh[nt] = *(const float2*)&sm[PB_HI + off];
            bl[nt] = *(const float2*)&sm[PB_HI + 4096 + off];
        }
        #pragma unroll
        for (int mt = 0; mt < 2; ++mt)
            #pragma unroll
            for (int nt = 0; nt < 4; ++nt) {
                mma_tf32(c[mt][nt], &ah[mt].x, &bh[nt].x);
                mma_tf32(c[mt][nt], &ah[mt].x, &bl[nt].x);
                mma_tf32(c[mt][nt], &al[mt].x, &bh[nt].x);
            }
    }
}

// ============================================================================
// Kernel 1: m = h @ W_msg^T  (tf32x3, packed fragments, prepacked W)
// ============================================================================
__global__ __launch_bounds__(256) void msg_gemm_mma(
    const float* __restrict__ h, const float* __restrict__ Wpk,
    float* __restrict__ m, int rows)
{
    extern __shared__ float sm[];
    const int tid = threadIdx.x;
    const int lane = tid & 31, wid = tid >> 5;
    const int g = lane >> 2, q = lane & 3;
    const int warp_m = wid >> 2, warp_n = wid & 3;
    const int m0 = warp_m * 32, n0 = warp_n * 32;
    const int row0 = blockIdx.x * 64;

    const float4* h4 = (const float4*)h;

    float c[2][4][4];
    #pragma unroll
    for (int mt = 0; mt < 2; ++mt)
        #pragma unroll
        for (int nt = 0; nt < 4; ++nt)
            #pragma unroll
            for (int k = 0; k < 4; ++k) c[mt][nt][k] = 0.f;

    for (int ch = 0; ch < 4; ++ch) {
        // stage A (64 x 32) split+packed
        #pragma unroll
        for (int i = tid; i < 512; i += 256) {
            const int r = i >> 3, j = i & 7;
            const int gr = row0 + r;
            float4 v = (gr < rows) ? h4[gr * 32 + ch * 8 + j]
                                   : make_float4(0.f, 0.f, 0.f, 0.f);
            stage_A_f4(sm, r, j, v);
        }
        // stage B: straight copy of prepacked chunk (hi+lo = 8192 floats)
        {
            const float4* wp = (const float4*)(Wpk + ch * 8192);
            #pragma unroll
            for (int i = tid; i < 2048; i += 256)
                *(float4*)&sm[PB_HI + i * 4] = wp[i];
        }
        __syncthreads();
        mma_chunk(sm, warp_m, warp_n, lane, c);
        __syncthreads();
    }

    // epilogue
    #pragma unroll
    for (int mt = 0; mt < 2; ++mt) {
        const int rlo = row0 + m0 + mt * 16 + g;
        const int rhi = rlo + 8;
        #pragma unroll
        for (int nt = 0; nt < 4; ++nt) {
            const int col = n0 + nt * 8 + q * 2;
            if (rlo < rows)
                *(float2*)&m[rlo * DD + col] = make_float2(c[mt][nt][0], c[mt][nt][1]);
            if (rhi < rows)
                *(float2*)&m[rhi * DD + col] = make_float2(c[mt][nt][2], c[mt][nt][3]);
        }
    }
}

// ============================================================================
// Kernel 2 (fused): gather agg tile in smem, then
// upd = relu([h|agg] @ W_upd^T + b); out = LN(h + upd)
// ============================================================================
__global__ __launch_bounds__(256) void update_ln_fused(
    const float* __restrict__ h, const float* __restrict__ m_,
    const float* __restrict__ rel_emb,
    const int* __restrict__ base, const int* __restrict__ sorted,
    const float* __restrict__ Wpk, const float* __restrict__ bupd,
    const float* __restrict__ lns, const float* __restrict__ lnb,
    float* __restrict__ out, int rows, int N, int ND4)
{
    extern __shared__ float sm[];
    float* smagg = sm + AGG_OFF;

    const int tid = threadIdx.x;
    const int lane = tid & 31, wid = tid >> 5;
    const int g = lane >> 2, q = lane & 3;
    const int warp_m = wid >> 2, warp_n = wid & 3;
    const int m0 = warp_m * 32, n0 = warp_n * 32;
    const int row0 = blockIdx.x * 64;

    const float4* h4 = (const float4*)h;
    const float4* m4 = (const float4*)m_;
    const float4* r4 = (const float4*)rel_emb;

    // ---- gather: agg rows [row0, row0+64) into smem (one warp per 8 rows) ----
    for (int rr8 = 0; rr8 < 8; ++rr8) {
        const int rr = wid * 8 + rr8;
        const int gr = row0 + rr;
        float4 a = make_float4(0.f, 0.f, 0.f, 0.f);
        if (gr < rows) {
            int nid, moff;
            if (gr < N) { nid = gr; moff = 0; }
            else        { nid = gr - N; moff = ND4; }
            const int i0 = nid ? __ldg(&base[nid - 1]) : 0;
            const int i1 = __ldg(&base[nid]);
            int i = i0;
            for (; i + 1 < i1; i += 2) {
                const int pA = __ldg(&sorted[i]);
                const int pB = __ldg(&sorted[i + 1]);
                const int sA = pA & 0x1FFFF, rA = pA >> 17;
                const int sB = pB & 0x1FFFF, rB = pB >> 17;
                const float4 mA = m4[moff + sA * 32 + lane];
                const float4 vA = r4[rA * 32 + lane];
                const float4 mB = m4[moff + sB * 32 + lane];
                const float4 vB = r4[rB * 32 + lane];
                a.x = fmaf(mA.x, vA.x, a.x); a.y = fmaf(mA.y, vA.y, a.y);
                a.z = fmaf(mA.z, vA.z, a.z); a.w = fmaf(mA.w, vA.w, a.w);
                a.x = fmaf(mB.x, vB.x, a.x); a.y = fmaf(mB.y, vB.y, a.y);
                a.z = fmaf(mB.z, vB.z, a.z); a.w = fmaf(mB.w, vB.w, a.w);
            }
            if (i < i1) {
                const int p = __ldg(&sorted[i]);
                const int s = p & 0x1FFFF, r = p >> 17;
                const float4 mv = m4[moff + s * 32 + lane];
                const float4 rv = r4[r * 32 + lane];
                a.x = fmaf(mv.x, rv.x, a.x); a.y = fmaf(mv.y, rv.y, a.y);
                a.z = fmaf(mv.z, rv.z, a.z); a.w = fmaf(mv.w, rv.w, a.w);
            }
        }
        *(float4*)&smagg[rr * AGG_STR + lane * 4] = a;
    }
    __syncthreads();

    // ---- GEMM: K=256 in 8 chunks (0-3: h, 4-7: smem agg) ----
    float c[2][4][4];
    #pragma unroll
    for (int mt = 0; mt < 2; ++mt)
        #pragma unroll
        for (int nt = 0; nt < 4; ++nt)
            #pragma unroll
            for (int k = 0; k < 4; ++k) c[mt][nt][k] = 0.f;

    for (int ch = 0; ch < 8; ++ch) {
        #pragma unroll
        for (int i = tid; i < 512; i += 256) {
            const int r = i >> 3, j = i & 7;
            float4 v;
            if (ch < 4) {
                const int gr = row0 + r;
                v = (gr < rows) ? h4[gr * 32 + ch * 8 + j]
                                : make_float4(0.f, 0.f, 0.f, 0.f);
            } else {
                v = *(const float4*)&smagg[r * AGG_STR + (ch & 3) * 32 + j * 4];
            }
            stage_A_f4(sm, r, j, v);
        }
        {
            const float4* wp = (const float4*)(Wpk + ch * 8192);
            #pragma unroll
            for (int i = tid; i < 2048; i += 256)
                *(float4*)&sm[PB_HI + i * 4] = wp[i];
        }
        __syncthreads();
        mma_chunk(sm, warp_m, warp_n, lane, c);
        __syncthreads();
    }

    // ---- epilogue: v = relu(C + b) + h, LN across row ----
    float2* red = (float2*)sm;          // red[row(64)][warp_n(4)] — packed area reusable

    float2 bias[4], lsc[4], lbi[4];
    #pragma unroll
    for (int nt = 0; nt < 4; ++nt) {
        const int col = n0 + nt * 8 + q * 2;
        bias[nt] = *(const float2*)&bupd[col];
        lsc[nt]  = *(const float2*)&lns[col];
        lbi[nt]  = *(const float2*)&lnb[col];
    }

    float s1v[2][2], s2v[2][2];
    #pragma unroll
    for (int mt = 0; mt < 2; ++mt) {
        const int rlo = row0 + m0 + mt * 16 + g;
        const int rhi = rlo + 8;
        float p1lo = 0.f, p2lo = 0.f, p1hi = 0.f, p2hi = 0.f;
        #pragma unroll
        for (int nt = 0; nt < 4; ++nt) {
            const int col = n0 + nt * 8 + q * 2;
            float2 hlo = (rlo < rows) ? *(const float2*)&h[rlo * DD + col]
                                      : make_float2(0.f, 0.f);
            float2 hhi = (rhi < rows) ? *(const float2*)&h[rhi * DD + col]
                                      : make_float2(0.f, 0.f);
            float v0 = fmaxf(c[mt][nt][0] + bias[nt].x, 0.f) + hlo.x;
            float v1 = fmaxf(c[mt][nt][1] + bias[nt].y, 0.f) + hlo.y;
            float v2 = fmaxf(c[mt][nt][2] + bias[nt].x, 0.f) + hhi.x;
            float v3 = fmaxf(c[mt][nt][3] + bias[nt].y, 0.f) + hhi.y;
            c[mt][nt][0] = v0; c[mt][nt][1] = v1;
            c[mt][nt][2] = v2; c[mt][nt][3] = v3;
            p1lo += v0 + v1;  p2lo += v0*v0 + v1*v1;
            p1hi += v2 + v3;  p2hi += v2*v2 + v3*v3;
        }
        s1v[mt][0] = p1lo; s2v[mt][0] = p2lo;
        s1v[mt][1] = p1hi; s2v[mt][1] = p2hi;
    }
    #pragma unroll
    for (int mt = 0; mt < 2; ++mt)
        #pragma unroll
        for (int hf = 0; hf < 2; ++hf) {
            float s1 = s1v[mt][hf], s2 = s2v[mt][hf];
            s1 += __shfl_xor_sync(0xffffffffu, s1, 1);
            s2 += __shfl_xor_sync(0xffffffffu, s2, 1);
            s1 += __shfl_xor_sync(0xffffffffu, s1, 2);
            s2 += __shfl_xor_sync(0xffffffffu, s2, 2);
            if (q == 0) {
                const int rl = m0 + mt * 16 + hf * 8 + g;
                red[rl * 4 + warp_n] = make_float2(s1, s2);
            }
        }
    __syncthreads();

    #pragma unroll
    for (int mt = 0; mt < 2; ++mt) {
        #pragma unroll
        for (int hf = 0; hf < 2; ++hf) {
            const int rl = m0 + mt * 16 + hf * 8 + g;
            const int gr = row0 + rl;
            float S1 = 0.f, S2 = 0.f;
            #pragma unroll
            for (int w = 0; w < 4; ++w) {
                float2 p = red[rl * 4 + w];
                S1 += p.x; S2 += p.y;
            }
            const float mu  = S1 * (1.f / 128.f);
            const float var = S2 * (1.f / 128.f) - mu * mu;
            const float rs  = rsqrtf(var + 1e-5f);
            if (gr < rows) {
                #pragma unroll
                for (int nt = 0; nt < 4; ++nt) {
                    const int col = n0 + nt * 8 + q * 2;
                    const float v0 = c[mt][nt][hf * 2 + 0];
                    const float v1 = c[mt][nt][hf * 2 + 1];
                    float2 o;
                    o.x = (v0 - mu) * rs * lsc[nt].x + lbi[nt].x;
                    o.y = (v1 - mu) * rs * lsc[nt].y + lbi[nt].y;
                    *(float2*)&out[gr * DD + col] = o;
                }
            }
        }
    }
}

// ============================================================================
// host
// ============================================================================
extern "C" void kernel_launch(void* const* d_in, const int* in_sizes, int n_in,
                              void* d_out, int out_size)
{
    const float* h    = (const float*)d_in[0];
    const float* Wmsg = (const float*)d_in[1];
    const float* rel  = (const float*)d_in[2];
    const float* Wupd = (const float*)d_in[3];
    const float* bupd = (const float*)d_in[4];
    const float* lns  = (const float*)d_in[5];
    const float* lnb  = (const float*)d_in[6];
    const int*   esrc = (const int*)d_in[7];
    const int*   etgt = (const int*)d_in[8];
    const int*   erel = (const int*)d_in[9];
    float* out = (float*)d_out;

    const int E    = in_sizes[7];
    const int rows = in_sizes[0] / DD;     // B*N
    const int N    = rows / 2;
    const int ND4  = N * DD / 4;
    const int tiles = (rows + 63) / 64;

    void *pm, *pc, *pb, *ps, *pwm, *pwu;
    cudaGetSymbolAddress(&pm, g_m);
    cudaGetSymbolAddress(&pc, g_cnt);
    cudaGetSymbolAddress(&pb, g_base);
    cudaGetSymbolAddress(&ps, g_sorted);
    cudaGetSymbolAddress(&pwm, g_Wm_pk);
    cudaGetSymbolAddress(&pwu, g_Wu_pk);
    float* d_m    = (float*)pm;
    int*   d_cnt  = (int*)pc;
    int*   d_base = (int*)pb;
    int*   d_sort = (int*)ps;
    float* d_wm   = (float*)pwm;
    float* d_wu   = (float*)pwu;

    cudaFuncSetAttribute(msg_gemm_mma,
        cudaFuncAttributeMaxDynamicSharedMemorySize, MSG_SM_BYTES);
    cudaFuncSetAttribute(update_ln_fused,
        cudaFuncAttributeMaxDynamicSharedMemorySize, UPD_SM_BYTES);

    // pre-split + pack weights (tiny)
    presplit_k<<<192, 256>>>(Wmsg, Wupd, d_wm, d_wu);

    // edge sort (counting sort by target)
    cudaMemsetAsync(d_cnt, 0, (size_t)N * sizeof(int), 0);
    hist_k<<<(E + 255) / 256, 256>>>(etgt, d_cnt, E);
    exscan_k<<<1, 1024>>>(d_cnt, d_base, N);
    fill_k<<<(E + 255) / 256, 256>>>(esrc, etgt, erel, d_base, d_sort, E);

    // m = h @ W_msg^T
    msg_gemm_mma<<<tiles, 256, MSG_SM_BYTES>>>(h, d_wm, d_m, rows);

    // fused: gather (CSR) + update GEMM + residual + layernorm
    update_ln_fused<<<tiles, 256, UPD_SM_BYTES>>>(
        h, d_m, rel, d_base, d_sort, d_wu, bupd, lns, lnb, out, rows, N, ND4);
}

// round 7
// speedup vs baseline: 1.1502x; 1.1502x over previous
#include <cuda_runtime.h>
#include <cstdint>

#define DD 128
#define MAXROWS (2*50000)
#define MAXN 50001
#define MAXE 800000

// scratch (__device__ globals — allocation-free rule)
__device__ float g_m[MAXROWS * DD];
__device__ float g_agg[MAXROWS * DD];
__device__ int   g_cnt[MAXN];
__device__ int   g_base[MAXN];
__device__ int   g_sorted[MAXE];
__device__ float g_Wm_pk[4 * 8192];   // W_msg  pre-split+packed: [ch][hi 4096 | lo 4096]
__device__ float g_Wu_pk[8 * 8192];   // W_upd  pre-split+packed

// ---------------------------------------------------------------------------
// helpers
// ---------------------------------------------------------------------------
__device__ __forceinline__ float to_tf32(float x) {
    uint32_t u;
    asm("cvt.rna.tf32.f32 %0, %1;" : "=r"(u) : "f"(x));
    return __uint_as_float(u);
}
__device__ __forceinline__ void split_tf32(float x, float& hi, float& lo) {
    hi = to_tf32(x);
    lo = to_tf32(x - hi);
}
__device__ __forceinline__ void mma_tf32(float* c, const float* a, const float* b) {
    asm volatile(
        "mma.sync.aligned.m16n8k8.row.col.f32.tf32.tf32.f32 "
        "{%0,%1,%2,%3}, {%4,%5,%6,%7}, {%8,%9}, {%0,%1,%2,%3};"
        : "+f"(c[0]), "+f"(c[1]), "+f"(c[2]), "+f"(c[3])
        : "r"(__float_as_uint(a[0])), "r"(__float_as_uint(a[1])),
          "r"(__float_as_uint(a[2])), "r"(__float_as_uint(a[3])),
          "r"(__float_as_uint(b[0])), "r"(__float_as_uint(b[1])));
}

// packed smem layout (floats)
//  A: [warp_m(2)][ks(4)][mt(2)][lane(32)][idx(4)]  = 2048 per buffer
//  B: [warp_n(4)][ks(4)][nt(4)][lane(32)][idx(2)]  = 4096 per buffer
#define PA_HI 0
#define PA_LO 2048
#define PB_HI 4096            // hi(4096) + lo(4096) contiguous
#define PACK_FLOATS 12288
#define SM_BYTES (PACK_FLOATS * 4)    // 49152

// ============================================================================
// Kernel P: pre-split W into tf32 hi/lo, packed in B-fragment order.
// ============================================================================
__global__ __launch_bounds__(256) void presplit_k(
    const float* __restrict__ Wm, const float* __restrict__ Wu,
    float* __restrict__ pm, float* __restrict__ pu)
{
    const int i = blockIdx.x * 256 + threadIdx.x;
    if (i < 16384) {                   // W_msg [128][128]
        const int n = i >> 7, k = i & 127;
        const int ch = k >> 5, kk = k & 31;
        const int warp_n = n >> 5, nt = (n >> 3) & 3, g = n & 7;
        const int q = kk & 3, khalf = (kk >> 2) & 1, ks = kk >> 3;
        const int inner = (((warp_n * 4 + ks) * 4 + nt) * 32 + g * 4 + q) * 2 + khalf;
        float hi, lo;
        split_tf32(Wm[i], hi, lo);
        pm[ch * 8192 + inner] = hi;
        pm[ch * 8192 + 4096 + inner] = lo;
    }
    const int j = i - 16384;
    if (j >= 0 && j < 32768) {         // W_upd [128][256]
        const int n = j >> 8, k = j & 255;
        const int ch = k >> 5, kk = k & 31;
        const int warp_n = n >> 5, nt = (n >> 3) & 3, g = n & 7;
        const int q = kk & 3, khalf = (kk >> 2) & 1, ks = kk >> 3;
        const int inner = (((warp_n * 4 + ks) * 4 + nt) * 32 + g * 4 + q) * 2 + khalf;
        float hi, lo;
        split_tf32(Wu[j], hi, lo);
        pu[ch * 8192 + inner] = hi;
        pu[ch * 8192 + 4096 + inner] = lo;
    }
}

// ============================================================================
// Edge sort (counting sort by target)
// ============================================================================
__global__ __launch_bounds__(256) void hist_k(const int* __restrict__ etgt,
                                              int* __restrict__ cnt, int E)
{
    int e = blockIdx.x * blockDim.x + threadIdx.x;
    if (e < E) atomicAdd(&cnt[etgt[e]], 1);
}

__global__ __launch_bounds__(1024) void exscan_k(const int* __restrict__ cnt,
                                                 int* __restrict__ base, int n)
{
    __shared__ int ws[32];
    __shared__ int carry_s;
    const int tid = threadIdx.x;
    const int lane = tid & 31, wid = tid >> 5;
    if (tid == 0) carry_s = 0;
    __syncthreads();

    for (int chunk = 0; chunk < n; chunk += 1024) {
        const int i = chunk + tid;
        const int x = (i < n) ? cnt[i] : 0;
        int v = x;
        #pragma unroll
        for (int o = 1; o < 32; o <<= 1) {
            int t = __shfl_up_sync(0xffffffffu, v, o);
            if (lane >= o) v += t;
        }
        if (lane == 31) ws[wid] = v;
        __syncthreads();
        if (wid == 0) {
            int w = ws[lane];
            #pragma unroll
            for (int o = 1; o < 32; o <<= 1) {
                int t = __shfl_up_sync(0xffffffffu, w, o);
                if (lane >= o) w += t;
            }
            ws[lane] = w;
        }
        __syncthreads();
        const int woff = (wid > 0) ? ws[wid - 1] : 0;
        const int carry = carry_s;
        const int incl = v + woff + carry;
        if (i < n) base[i] = incl - x;
        __syncthreads();
        if (tid == 1023) carry_s = incl;
        __syncthreads();
    }
}

__global__ __launch_bounds__(256) void fill_k(
    const int* __restrict__ esrc, const int* __restrict__ etgt,
    const int* __restrict__ erel, int* __restrict__ base,
    int* __restrict__ sorted, int E)
{
    int e = blockIdx.x * blockDim.x + threadIdx.x;
    if (e >= E) return;
    const int t = etgt[e];
    const int pos = atomicAdd(&base[t], 1);
    sorted[pos] = esrc[e] | (erel[e] << 17);
}

// ---------------------------------------------------------------------------
// shared GEMM building blocks (fragment-packed smem)
// ---------------------------------------------------------------------------
__device__ __forceinline__ void stage_A_f4(float* sm, int r, int j, float4 v)
{
    float4 hi, lo;
    split_tf32(v.x, hi.x, lo.x);
    split_tf32(v.y, hi.y, lo.y);
    split_tf32(v.z, hi.z, lo.z);
    split_tf32(v.w, hi.w, lo.w);
    const int warp_m = r >> 5, mt = (r >> 4) & 1, g = r & 7, hi8 = (r >> 3) & 1;
    const int khalf = j & 1, ks = j >> 1;
    const int basei = ((warp_m * 4 + ks) * 2 + mt) * 128 + g * 16 + (hi8 + 2 * khalf);
    float* ph = sm + PA_HI + basei;
    float* pl = sm + PA_LO + basei;
    ph[0] = hi.x; ph[4] = hi.y; ph[8] = hi.z; ph[12] = hi.w;
    pl[0] = lo.x; pl[4] = lo.y; pl[8] = lo.z; pl[12] = lo.w;
}

__device__ __forceinline__ void mma_chunk(const float* sm, int warp_m, int warp_n,
                                          int lane, float c[2][4][4])
{
    #pragma unroll
    for (int ks = 0; ks < 4; ++ks) {
        float4 ah[2], al[2];
        #pragma unroll
        for (int mt = 0; mt < 2; ++mt) {
            const int off = ((warp_m * 4 + ks) * 2 + mt) * 128 + lane * 4;
            ah[mt] = *(const float4*)&sm[PA_HI + off];
            al[mt] = *(const float4*)&sm[PA_LO + off];
        }
        float2 bh[4], bl[4];
        #pragma unroll
        for (int nt = 0; nt < 4; ++nt) {
            const int off = ((warp_n * 4 + ks) * 4 + nt) * 64 + lane * 2;
            bh[nt] = *(const float2*)&sm[PB_HI + off];
            bl[nt] = *(const float2*)&sm[PB_HI + 4096 + off];
        }
        #pragma unroll
        for (int mt = 0; mt < 2; ++mt)
            #pragma unroll
            for (int nt = 0; nt < 4; ++nt) {
                mma_tf32(c[mt][nt], &ah[mt].x, &bh[nt].x);
                mma_tf32(c[mt][nt], &ah[mt].x, &bl[nt].x);
                mma_tf32(c[mt][nt], &al[mt].x, &bh[nt].x);
            }
    }
}

// ============================================================================
// Kernel 1: m = h @ W_msg^T  (tf32x3, packed fragments, prepacked W)
// ============================================================================
__global__ __launch_bounds__(256) void msg_gemm_mma(
    const float* __restrict__ h, const float* __restrict__ Wpk,
    float* __restrict__ m, int rows)
{
    extern __shared__ float sm[];
    const int tid = threadIdx.x;
    const int lane = tid & 31, wid = tid >> 5;
    const int g = lane >> 2, q = lane & 3;
    const int warp_m = wid >> 2, warp_n = wid & 3;
    const int m0 = warp_m * 32, n0 = warp_n * 32;
    const int row0 = blockIdx.x * 64;

    const float4* h4 = (const float4*)h;

    float c[2][4][4];
    #pragma unroll
    for (int mt = 0; mt < 2; ++mt)
        #pragma unroll
        for (int nt = 0; nt < 4; ++nt)
            #pragma unroll
            for (int k = 0; k < 4; ++k) c[mt][nt][k] = 0.f;

    for (int ch = 0; ch < 4; ++ch) {
        #pragma unroll
        for (int i = tid; i < 512; i += 256) {
            const int r = i >> 3, j = i & 7;
            const int gr = row0 + r;
            float4 v = (gr < rows) ? h4[gr * 32 + ch * 8 + j]
                                   : make_float4(0.f, 0.f, 0.f, 0.f);
            stage_A_f4(sm, r, j, v);
        }
        {
            const float4* wp = (const float4*)(Wpk + ch * 8192);
            #pragma unroll
            for (int i = tid; i < 2048; i += 256)
                *(float4*)&sm[PB_HI + i * 4] = wp[i];
        }
        __syncthreads();
        mma_chunk(sm, warp_m, warp_n, lane, c);
        __syncthreads();
    }

    #pragma unroll
    for (int mt = 0; mt < 2; ++mt) {
        const int rlo = row0 + m0 + mt * 16 + g;
        const int rhi = rlo + 8;
        #pragma unroll
        for (int nt = 0; nt < 4; ++nt) {
            const int col = n0 + nt * 8 + q * 2;
            if (rlo < rows)
                *(float2*)&m[rlo * DD + col] = make_float2(c[mt][nt][0], c[mt][nt][1]);
            if (rhi < rows)
                *(float2*)&m[rhi * DD + col] = make_float2(c[mt][nt][2], c[mt][nt][3]);
        }
    }
}

// ============================================================================
// Kernel 2: CSR gather. One warp per target node, both batches, no atomics.
// (standalone — full-chip latency hiding; the R6 fusion regressed)
// ============================================================================
__global__ __launch_bounds__(256) void gather_csr(
    const float* __restrict__ m, const float* __restrict__ rel_emb,
    const int* __restrict__ base, const int* __restrict__ sorted,
    float* __restrict__ agg, int N, int ND)
{
    const int nid = blockIdx.x * 8 + (threadIdx.x >> 5);
    if (nid >= N) return;
    const int lane = threadIdx.x & 31;

    const int start = (nid == 0) ? 0 : __ldg(&base[nid - 1]);
    const int end = __ldg(&base[nid]);

    const float4* m4 = (const float4*)m;
    const float4* r4 = (const float4*)rel_emb;
    const int ND4 = ND / 4;

    float4 a0 = make_float4(0.f,0.f,0.f,0.f);
    float4 a1 = make_float4(0.f,0.f,0.f,0.f);

    int i = start;
    for (; i + 1 < end; i += 2) {
        const int pA = __ldg(&sorted[i]);
        const int pB = __ldg(&sorted[i + 1]);
        const int sA = pA & 0x1FFFF, rA = pA >> 17;
        const int sB = pB & 0x1FFFF, rB = pB >> 17;
        const float4 rvA = r4[rA * 32 + lane];
        const float4 m0A = m4[sA * 32 + lane];
        const float4 m1A = m4[ND4 + sA * 32 + lane];
        const float4 rvB = r4[rB * 32 + lane];
        const float4 m0B = m4[sB * 32 + lane];
        const float4 m1B = m4[ND4 + sB * 32 + lane];
        a0.x = fmaf(m0A.x, rvA.x, a0.x); a0.y = fmaf(m0A.y, rvA.y, a0.y);
        a0.z = fmaf(m0A.z, rvA.z, a0.z); a0.w = fmaf(m0A.w, rvA.w, a0.w);
        a1.x = fmaf(m1A.x, rvA.x, a1.x); a1.y = fmaf(m1A.y, rvA.y, a1.y);
        a1.z = fmaf(m1A.z, rvA.z, a1.z); a1.w = fmaf(m1A.w, rvA.w, a1.w);
        a0.x = fmaf(m0B.x, rvB.x, a0.x); a0.y = fmaf(m0B.y, rvB.y, a0.y);
        a0.z = fmaf(m0B.z, rvB.z, a0.z); a0.w = fmaf(m0B.w, rvB.w, a0.w);
        a1.x = fmaf(m1B.x, rvB.x, a1.x); a1.y = fmaf(m1B.y, rvB.y, a1.y);
        a1.z = fmaf(m1B.z, rvB.z, a1.z); a1.w = fmaf(m1B.w, rvB.w, a1.w);
    }
    if (i < end) {
        const int p = __ldg(&sorted[i]);
        const int s = p & 0x1FFFF, r = p >> 17;
        const float4 rv = r4[r * 32 + lane];
        const float4 m0 = m4[s * 32 + lane];
        const float4 m1 = m4[ND4 + s * 32 + lane];
        a0.x = fmaf(m0.x, rv.x, a0.x); a0.y = fmaf(m0.y, rv.y, a0.y);
        a0.z = fmaf(m0.z, rv.z, a0.z); a0.w = fmaf(m0.w, rv.w, a0.w);
        a1.x = fmaf(m1.x, rv.x, a1.x); a1.y = fmaf(m1.y, rv.y, a1.y);
        a1.z = fmaf(m1.z, rv.z, a1.z); a1.w = fmaf(m1.w, rv.w, a1.w);
    }

    float4* agg4 = (float4*)agg;
    agg4[nid * 32 + lane] = a0;
    agg4[ND4 + nid * 32 + lane] = a1;
}

// ============================================================================
// Kernel 3: upd = relu([h|agg] @ W_upd^T + b); out = LN(h + upd)
// tf32x3 packed fragments, prepacked W; agg read from gmem.
// ============================================================================
__global__ __launch_bounds__(256) void update_ln_mma(
    const float* __restrict__ h, const float* __restrict__ agg,
    const float* __restrict__ Wpk, const float* __restrict__ bupd,
    const float* __restrict__ lns, const float* __restrict__ lnb,
    float* __restrict__ out, int rows)
{
    extern __shared__ float sm[];
    const int tid = threadIdx.x;
    const int lane = tid & 31, wid = tid >> 5;
    const int g = lane >> 2, q = lane & 3;
    const int warp_m = wid >> 2, warp_n = wid & 3;
    const int m0 = warp_m * 32, n0 = warp_n * 32;
    const int row0 = blockIdx.x * 64;

    const float4* h4 = (const float4*)h;
    const float4* a4 = (const float4*)agg;

    float c[2][4][4];
    #pragma unroll
    for (int mt = 0; mt < 2; ++mt)
        #pragma unroll
        for (int nt = 0; nt < 4; ++nt)
            #pragma unroll
            for (int k = 0; k < 4; ++k) c[mt][nt][k] = 0.f;

    for (int ch = 0; ch < 8; ++ch) {
        const float4* src4 = (ch < 4) ? h4 : a4;
        const int scol8 = (ch & 3) * 8;
        #pragma unroll
        for (int i = tid; i < 512; i += 256) {
            const int r = i >> 3, j = i & 7;
            const int gr = row0 + r;
            float4 v = (gr < rows) ? src4[gr * 32 + scol8 + j]
                                   : make_float4(0.f, 0.f, 0.f, 0.f);
            stage_A_f4(sm, r, j, v);
        }
        {
            const float4* wp = (const float4*)(Wpk + ch * 8192);
            #pragma unroll
            for (int i = tid; i < 2048; i += 256)
                *(float4*)&sm[PB_HI + i * 4] = wp[i];
        }
        __syncthreads();
        mma_chunk(sm, warp_m, warp_n, lane, c);
        __syncthreads();
    }

    // ---- epilogue: v = relu(C + b) + h, LN across row ----
    float2* red = (float2*)sm;          // red[row(64)][warp_n(4)]

    float2 bias[4], lsc[4], lbi[4];
    #pragma unroll
    for (int nt = 0; nt < 4; ++nt) {
        const int col = n0 + nt * 8 + q * 2;
        bias[nt] = *(const float2*)&bupd[col];
        lsc[nt]  = *(const float2*)&lns[col];
        lbi[nt]  = *(const float2*)&lnb[col];
    }

    float s1v[2][2], s2v[2][2];
    #pragma unroll
    for (int mt = 0; mt < 2; ++mt) {
        const int rlo = row0 + m0 + mt * 16 + g;
        const int rhi = rlo + 8;
        float p1lo = 0.f, p2lo = 0.f, p1hi = 0.f, p2hi = 0.f;
        #pragma unroll
        for (int nt = 0; nt < 4; ++nt) {
            const int col = n0 + nt * 8 + q * 2;
            float2 hlo = (rlo < rows) ? *(const float2*)&h[rlo * DD + col]
                                      : make_float2(0.f, 0.f);
            float2 hhi = (rhi < rows) ? *(const float2*)&h[rhi * DD + col]
                                      : make_float2(0.f, 0.f);
            float v0 = fmaxf(c[mt][nt][0] + bias[nt].x, 0.f) + hlo.x;
            float v1 = fmaxf(c[mt][nt][1] + bias[nt].y, 0.f) + hlo.y;
            float v2 = fmaxf(c[mt][nt][2] + bias[nt].x, 0.f) + hhi.x;
            float v3 = fmaxf(c[mt][nt][3] + bias[nt].y, 0.f) + hhi.y;
            c[mt][nt][0] = v0; c[mt][nt][1] = v1;
            c[mt][nt][2] = v2; c[mt][nt][3] = v3;
            p1lo += v0 + v1;  p2lo += v0*v0 + v1*v1;
            p1hi += v2 + v3;  p2hi += v2*v2 + v3*v3;
        }
        s1v[mt][0] = p1lo; s2v[mt][0] = p2lo;
        s1v[mt][1] = p1hi; s2v[mt][1] = p2hi;
    }
    #pragma unroll
    for (int mt = 0; mt < 2; ++mt)
        #pragma unroll
        for (int hf = 0; hf < 2; ++hf) {
            float s1 = s1v[mt][hf], s2 = s2v[mt][hf];
            s1 += __shfl_xor_sync(0xffffffffu, s1, 1);
            s2 += __shfl_xor_sync(0xffffffffu, s2, 1);
            s1 += __shfl_xor_sync(0xffffffffu, s1, 2);
            s2 += __shfl_xor_sync(0xffffffffu, s2, 2);
            if (q == 0) {
                const int rl = m0 + mt * 16 + hf * 8 + g;
                red[rl * 4 + warp_n] = make_float2(s1, s2);
            }
        }
    __syncthreads();

    #pragma unroll
    for (int mt = 0; mt < 2; ++mt) {
        #pragma unroll
        for (int hf = 0; hf < 2; ++hf) {
            const int rl = m0 + mt * 16 + hf * 8 + g;
            const int gr = row0 + rl;
            float S1 = 0.f, S2 = 0.f;
            #pragma unroll
            for (int w = 0; w < 4; ++w) {
                float2 p = red[rl * 4 + w];
                S1 += p.x; S2 += p.y;
            }
            const float mu  = S1 * (1.f / 128.f);
            const float var = S2 * (1.f / 128.f) - mu * mu;
            const float rs  = rsqrtf(var + 1e-5f);
            if (gr < rows) {
                #pragma unroll
                for (int nt = 0; nt < 4; ++nt) {
                    const int col = n0 + nt * 8 + q * 2;
                    const float v0 = c[mt][nt][hf * 2 + 0];
                    const float v1 = c[mt][nt][hf * 2 + 1];
                    float2 o;
                    o.x = (v0 - mu) * rs * lsc[nt].x + lbi[nt].x;
                    o.y = (v1 - mu) * rs * lsc[nt].y + lbi[nt].y;
                    *(float2*)&out[gr * DD + col] = o;
                }
            }
        }
    }
}

// ============================================================================
// host
// ============================================================================
extern "C" void kernel_launch(void* const* d_in, const int* in_sizes, int n_in,
                              void* d_out, int out_size)
{
    const float* h    = (const float*)d_in[0];
    const float* Wmsg = (const float*)d_in[1];
    const float* rel  = (const float*)d_in[2];
    const float* Wupd = (const float*)d_in[3];
    const float* bupd = (const float*)d_in[4];
    const float* lns  = (const float*)d_in[5];
    const float* lnb  = (const float*)d_in[6];
    const int*   esrc = (const int*)d_in[7];
    const int*   etgt = (const int*)d_in[8];
    const int*   erel = (const int*)d_in[9];
    float* out = (float*)d_out;

    const int E    = in_sizes[7];
    const int rows = in_sizes[0] / DD;     // B*N
    const int N    = rows / 2;
    const int ND   = N * DD;
    const int tiles = (rows + 63) / 64;

    void *pm, *pa, *pc, *pb, *ps, *pwm, *pwu;
    cudaGetSymbolAddress(&pm, g_m);
    cudaGetSymbolAddress(&pa, g_agg);
    cudaGetSymbolAddress(&pc, g_cnt);
    cudaGetSymbolAddress(&pb, g_base);
    cudaGetSymbolAddress(&ps, g_sorted);
    cudaGetSymbolAddress(&pwm, g_Wm_pk);
    cudaGetSymbolAddress(&pwu, g_Wu_pk);
    float* d_m    = (float*)pm;
    float* d_agg  = (float*)pa;
    int*   d_cnt  = (int*)pc;
    int*   d_base = (int*)pb;
    int*   d_sort = (int*)ps;
    float* d_wm   = (float*)pwm;
    float* d_wu   = (float*)pwu;

    cudaFuncSetAttribute(msg_gemm_mma,
        cudaFuncAttributeMaxDynamicSharedMemorySize, SM_BYTES);
    cudaFuncSetAttribute(update_ln_mma,
        cudaFuncAttributeMaxDynamicSharedMemorySize, SM_BYTES);

    // pre-split + pack weights (tiny)
    presplit_k<<<192, 256>>>(Wmsg, Wupd, d_wm, d_wu);

    // edge sort (counting sort by target)
    cudaMemsetAsync(d_cnt, 0, (size_t)N * sizeof(int), 0);
    hist_k<<<(E + 255) / 256, 256>>>(etgt, d_cnt, E);
    exscan_k<<<1, 1024>>>(d_cnt, d_base, N);
    fill_k<<<(E + 255) / 256, 256>>>(esrc, etgt, erel, d_base, d_sort, E);

    // m = h @ W_msg^T
    msg_gemm_mma<<<tiles, 256, SM_BYTES>>>(h, d_wm, d_m, rows);

    // agg[t] = sum_{e: tgt=t} m[src_e] * rel_emb[rel_e]
    gather_csr<<<(N + 7) / 8, 256>>>(d_m, rel, d_base, d_sort, d_agg, N, ND);

    // update + residual + layernorm
    update_ln_mma<<<tiles, 256, SM_BYTES>>>(h, d_agg, d_wu, bupd, lns, lnb, out, rows);
}